// round 16
// baseline (speedup 1.0000x reference)
#include <cuda_runtime.h>
#include <cuda_fp16.h>
#include <cstdint>

#define N_NODES 50000
#define N_EDGES 800000
#define IN_F 128
#define OUT_F 128
#define HEADS 4
#define HEAD_DIM 32

// ---------------- scratch (device globals; no allocation allowed) ----------------
__device__ __half g_wb[3 * 128 * 128];      // packed qkv weights: [qkv][outcol][f]
__device__ float  g_bb[384];                // packed qkv biases
__device__ __half g_q[N_NODES * IN_F];      // fp16 q/k/v
__device__ __half g_k[N_NODES * IN_F];
__device__ __half g_v[N_NODES * IN_F];
__device__ float  g_den[N_NODES * HEADS];   // segment sum of exp(score)
__device__ float  g_agg[N_NODES * OUT_F];   // UNNORMALIZED sum of exp(s)*v

__device__ __forceinline__ void mma16816(float* c, const uint32_t* a,
                                         uint32_t b0, uint32_t b1) {
    asm volatile(
        "mma.sync.aligned.m16n8k16.row.col.f32.f16.f16.f32 "
        "{%0,%1,%2,%3}, {%4,%5,%6,%7}, {%8,%9}, {%0,%1,%2,%3};"
        : "+f"(c[0]), "+f"(c[1]), "+f"(c[2]), "+f"(c[3])
        : "r"(a[0]), "r"(a[1]), "r"(a[2]), "r"(a[3]), "r"(b0), "r"(b1));
}

// ---------------- prep: zero agg/den + pack qkv weights/biases ---------------
__global__ void prep_kernel(const float* __restrict__ wq, const float* __restrict__ bq,
                            const float* __restrict__ wk, const float* __restrict__ bk,
                            const float* __restrict__ wv, const float* __restrict__ bv) {
    int idx = blockIdx.x * blockDim.x + threadIdx.x;       // 1.6M threads
    if (idx < N_NODES * OUT_F / 4)
        ((float4*)g_agg)[idx] = make_float4(0.f, 0.f, 0.f, 0.f);
    if (idx < N_NODES * HEADS)
        g_den[idx] = 0.f;
    if (idx < 3 * 128 * 128) {
        int arr = idx >> 14;                 // 0=q,1=k,2=v
        int rem = idx & 16383;
        int j = rem >> 7, f = rem & 127;     // out col j = h*32+d
        int h = j >> 5, d = j & 31;
        const float* w = arr == 0 ? wq : arr == 1 ? wk : wv;
        g_wb[idx] = __float2half_rn(w[h * IN_F * HEAD_DIM + f * HEAD_DIM + d]);
    }
    if (idx < 384) {
        int arr = idx >> 7, j = idx & 127;
        const float* b = arr == 0 ? bq : arr == 1 ? bk : bv;
        g_bb[idx] = b[j];
    }
}

// ---------------- tensor-core QKV projection (A staged ONCE from fp32 x) ----
#define LDA 136
#define PROJ_SMEM (2 * 128 * 136 * 2)
__global__ void __launch_bounds__(256) proj_mma_kernel(const float* __restrict__ x) {
    extern __shared__ __half sm[];
    __half* As = sm;                  // [128][LDA]
    __half* Bs = sm + 128 * LDA;      // [128][LDA]
    const int tid = threadIdx.x;
    const int mbase = blockIdx.x * 128;

    {   // load A tile once, fp32 -> fp16 convert in-flight (clamped rows)
        int r = tid >> 1, hoff = (tid & 1) * 64;
        int node = mbase + r; if (node >= N_NODES) node = N_NODES - 1;
        const float4* src = (const float4*)(x + (size_t)node * IN_F + hoff);
        __half2 tmp[32];
#pragma unroll
        for (int i = 0; i < 16; i++) {
            float4 v = src[i];
            tmp[2 * i + 0] = __floats2half2_rn(v.x, v.y);
            tmp[2 * i + 1] = __floats2half2_rn(v.z, v.w);
        }
        uint4* dst = (uint4*)(As + r * LDA + hoff);
#pragma unroll
        for (int i = 0; i < 8; i++) dst[i] = ((const uint4*)tmp)[i];
    }

    const int warp = tid >> 5, lane = tid & 31;
    const int wm = (warp & 3) * 32;
    const int wn = (warp >> 2) * 64;
    const int g = lane >> 2, tg = lane & 3;

    for (int y = 0; y < 3; y++) {
        if (y > 0) __syncthreads();          // all warps done reading prev Bs
        {   // load B tile for this y
            int n = tid >> 1, hoff = (tid & 1) * 64;
            const uint4* src = (const uint4*)(g_wb + y * 16384 + n * 128 + hoff);
            uint4* dst = (uint4*)(Bs + n * LDA + hoff);
#pragma unroll
            for (int i = 0; i < 8; i++) dst[i] = src[i];
        }
        __syncthreads();

        float c[2][8][4];
#pragma unroll
        for (int tm = 0; tm < 2; tm++)
#pragma unroll
            for (int tn = 0; tn < 8; tn++)
#pragma unroll
                for (int i = 0; i < 4; i++) c[tm][tn][i] = 0.f;

#pragma unroll
        for (int ks = 0; ks < 8; ks++) {
            const int k0 = ks * 16 + tg * 2;
            uint32_t a[2][4];
#pragma unroll
            for (int tm = 0; tm < 2; tm++) {
                const __half* ap = As + (wm + tm * 16 + g) * LDA;
                a[tm][0] = *(const uint32_t*)(ap + k0);
                a[tm][1] = *(const uint32_t*)(ap + 8 * LDA + k0);
                a[tm][2] = *(const uint32_t*)(ap + k0 + 8);
                a[tm][3] = *(const uint32_t*)(ap + 8 * LDA + k0 + 8);
            }
#pragma unroll
            for (int tn = 0; tn < 8; tn++) {
                const __half* bp = Bs + (wn + tn * 8 + g) * LDA + k0;
                uint32_t b0 = *(const uint32_t*)(bp);
                uint32_t b1 = *(const uint32_t*)(bp + 8);
#pragma unroll
                for (int tm = 0; tm < 2; tm++)
                    mma16816(c[tm][tn], a[tm], b0, b1);
            }
        }

        __half* outp = (y == 0) ? g_q : (y == 1) ? g_k : g_v;
        const float* bb = g_bb + y * 128;
#pragma unroll
        for (int tn = 0; tn < 8; tn++) {
            const int col = wn + tn * 8 + tg * 2;
            const float2 bias = *(const float2*)(bb + col);
#pragma unroll
            for (int tm = 0; tm < 2; tm++) {
                int row0 = mbase + wm + tm * 16 + g;
                if (row0 < N_NODES)
                    *(__half2*)(outp + (size_t)row0 * IN_F + col) =
                        __floats2half2_rn(c[tm][tn][0] + bias.x, c[tm][tn][1] + bias.y);
                int row1 = row0 + 8;
                if (row1 < N_NODES)
                    *(__half2*)(outp + (size_t)row1 * IN_F + col) =
                        __floats2half2_rn(c[tm][tn][2] + bias.x, c[tm][tn][3] + bias.y);
            }
        }
    }
}

// ---------------- FUSED edge pass, 4 edges per warp -------------------------
__global__ void __launch_bounds__(256) edge_kernel(const int* __restrict__ ei) {
    const int w = (blockIdx.x * blockDim.x + threadIdx.x) >> 5;
    const int lane = threadIdx.x & 31;
    const int e0 = w * 4;
    if (e0 >= N_EDGES) return;

    int se[4], te[4];
#pragma unroll
    for (int i = 0; i < 4; i++) {
        se[i] = __ldg(&ei[e0 + i]);
        te[i] = __ldg(&ei[N_EDGES + e0 + i]);
    }

    float p[4];
#pragma unroll
    for (int i = 0; i < 4; i++) {
        const uint2 qa = ((const uint2*)(g_q + (size_t)te[i] * IN_F))[lane];
        const uint2 ka = ((const uint2*)(g_k + (size_t)se[i] * IN_F))[lane];
        float2 q0 = __half22float2(*(const __half2*)&qa.x);
        float2 q1 = __half22float2(*(const __half2*)&qa.y);
        float2 k0 = __half22float2(*(const __half2*)&ka.x);
        float2 k1 = __half22float2(*(const __half2*)&ka.y);
        p[i] = q0.x * k0.x + q0.y * k0.y + q1.x * k1.x + q1.y * k1.y;
    }

#pragma unroll
    for (int off = 4; off > 0; off >>= 1)
#pragma unroll
        for (int i = 0; i < 4; i++)
            p[i] += __shfl_xor_sync(0xffffffffu, p[i], off);

    float ex[4];
#pragma unroll
    for (int i = 0; i < 4; i++) ex[i] = __expf(p[i]);

#pragma unroll
    for (int i = 0; i < 4; i++) {
        const uint2 va = ((const uint2*)(g_v + (size_t)se[i] * IN_F))[lane];
        float2 v0 = __half22float2(*(const __half2*)&va.x);
        float2 v1 = __half22float2(*(const __half2*)&va.y);
        float* dst = g_agg + (size_t)te[i] * OUT_F + lane * 4;
        asm volatile("red.global.add.v4.f32 [%0], {%1, %2, %3, %4};"
                     :: "l"(dst), "f"(ex[i] * v0.x), "f"(ex[i] * v0.y),
                        "f"(ex[i] * v1.x), "f"(ex[i] * v1.y) : "memory");
    }

    const int i = lane & 7;
    if (i < 4)
        atomicAdd(&g_den[te[i] * HEADS + (lane >> 3)], ex[i]);
}

// ---------------- output GEMM: split-fp16 HMMA, M-tile 128 ------------------
// out = (agg/den) @ wo^T + bo via a_hi*b_hi + a_hi*b_lo + a_lo*b_hi.
// B (wo) is read fp32 and hi/lo-split during staging (traffic-neutral vs fp16x2).
#define OUT_SMEM (4 * 128 * 136 * 2)
__global__ void __launch_bounds__(256) out_mma_kernel(const float* __restrict__ wo,
                                                      const float* __restrict__ bo,
                                                      float* __restrict__ out) {
    extern __shared__ __half sm[];
    __half* Ah = sm;                       // [128][LDA]
    __half* Al = sm + 128 * LDA;
    __half* Bh = sm + 2 * 128 * LDA;
    __half* Bl = sm + 3 * 128 * LDA;
    const int tid = threadIdx.x;
    const int mbase = blockIdx.x * 128;

    {   // stage B tiles: read wo fp32 row n (= [outcol][f], fragment-ready), split
        int n = tid >> 1, hoff = (tid & 1) * 64;
        const float4* src = (const float4*)(wo + n * 128 + hoff);
        __half* bh = Bh + n * LDA + hoff;
        __half* bl = Bl + n * LDA + hoff;
#pragma unroll
        for (int i = 0; i < 16; i++) {      // 16 float4 = 64 cols
            float4 v = src[i];
            __half h0 = __float2half_rn(v.x), h1 = __float2half_rn(v.y);
            __half h2 = __float2half_rn(v.z), h3 = __float2half_rn(v.w);
            ((__half2*)(bh + i * 4))[0] = __halves2half2(h0, h1);
            ((__half2*)(bh + i * 4))[1] = __halves2half2(h2, h3);
            ((__half2*)(bl + i * 4))[0] = __floats2half2_rn(
                v.x - __half2float(h0), v.y - __half2float(h1));
            ((__half2*)(bl + i * 4))[1] = __floats2half2_rn(
                v.z - __half2float(h2), v.w - __half2float(h3));
        }
    }
    {   // stage A tiles: normalize agg, split to hi/lo fp16
        int r = tid >> 1, hoff = (tid & 1) * 64;
        int node = mbase + r; if (node >= N_NODES) node = N_NODES - 1;
        const float* dn = g_den + node * HEADS;
        float rc[2];                        // heads hoff/32, hoff/32+1
#pragma unroll
        for (int hh = 0; hh < 2; hh++) {
            float d = dn[(hoff >> 5) + hh];
            rc[hh] = d > 0.f ? __frcp_rn(d) : 0.f;
        }
        const float4* src = (const float4*)(g_agg + (size_t)node * OUT_F + hoff);
        __half* ah = Ah + r * LDA + hoff;
        __half* al = Al + r * LDA + hoff;
#pragma unroll
        for (int i = 0; i < 16; i++) {      // 16 float4 = 64 cols
            float4 v = src[i];
            float rr = rc[i >> 3];          // head boundary at col 32 (i=8)
            float a0 = v.x * rr, a1 = v.y * rr, a2 = v.z * rr, a3 = v.w * rr;
            __half h0 = __float2half_rn(a0), h1 = __float2half_rn(a1);
            __half h2 = __float2half_rn(a2), h3 = __float2half_rn(a3);
            ((__half2*)(ah + i * 4))[0] = __halves2half2(h0, h1);
            ((__half2*)(ah + i * 4))[1] = __halves2half2(h2, h3);
            ((__half2*)(al + i * 4))[0] = __floats2half2_rn(
                a0 - __half2float(h0), a1 - __half2float(h1));
            ((__half2*)(al + i * 4))[1] = __floats2half2_rn(
                a2 - __half2float(h2), a3 - __half2float(h3));
        }
    }
    __syncthreads();

    const int warp = tid >> 5, lane = tid & 31;
    const int wm = (warp & 3) * 32;
    const int wn = (warp >> 2) * 64;
    const int g = lane >> 2, tg = lane & 3;

    float c[2][8][4];
#pragma unroll
    for (int tm = 0; tm < 2; tm++)
#pragma unroll
        for (int tn = 0; tn < 8; tn++)
#pragma unroll
            for (int i = 0; i < 4; i++) c[tm][tn][i] = 0.f;

#pragma unroll
    for (int ks = 0; ks < 8; ks++) {
        const int k0 = ks * 16 + tg * 2;
        uint32_t ah[2][4], al[2][4];
#pragma unroll
        for (int tm = 0; tm < 2; tm++) {
            const __half* aph = Ah + (wm + tm * 16 + g) * LDA;
            const __half* apl = Al + (wm + tm * 16 + g) * LDA;
            ah[tm][0] = *(const uint32_t*)(aph + k0);
            ah[tm][1] = *(const uint32_t*)(aph + 8 * LDA + k0);
            ah[tm][2] = *(const uint32_t*)(aph + k0 + 8);
            ah[tm][3] = *(const uint32_t*)(aph + 8 * LDA + k0 + 8);
            al[tm][0] = *(const uint32_t*)(apl + k0);
            al[tm][1] = *(const uint32_t*)(apl + 8 * LDA + k0);
            al[tm][2] = *(const uint32_t*)(apl + k0 + 8);
            al[tm][3] = *(const uint32_t*)(apl + 8 * LDA + k0 + 8);
        }
#pragma unroll
        for (int tn = 0; tn < 8; tn++) {
            const __half* bph = Bh + (wn + tn * 8 + g) * LDA + k0;
            const __half* bpl = Bl + (wn + tn * 8 + g) * LDA + k0;
            uint32_t bh0 = *(const uint32_t*)(bph);
            uint32_t bh1 = *(const uint32_t*)(bph + 8);
            uint32_t bl0 = *(const uint32_t*)(bpl);
            uint32_t bl1 = *(const uint32_t*)(bpl + 8);
#pragma unroll
            for (int tm = 0; tm < 2; tm++) {
                mma16816(c[tm][tn], al[tm], bh0, bh1);   // small terms first
                mma16816(c[tm][tn], ah[tm], bl0, bl1);
                mma16816(c[tm][tn], ah[tm], bh0, bh1);
            }
        }
    }

#pragma unroll
    for (int tn = 0; tn < 8; tn++) {
        const int col = wn + tn * 8 + tg * 2;
        const float2 bias = *(const float2*)(bo + col);
#pragma unroll
        for (int tm = 0; tm < 2; tm++) {
            int row0 = mbase + wm + tm * 16 + g;
            if (row0 < N_NODES)
                *(float2*)(out + (size_t)row0 * OUT_F + col) =
                    make_float2(c[tm][tn][0] + bias.x, c[tm][tn][1] + bias.y);
            int row1 = row0 + 8;
            if (row1 < N_NODES)
                *(float2*)(out + (size_t)row1 * OUT_F + col) =
                    make_float2(c[tm][tn][2] + bias.x, c[tm][tn][3] + bias.y);
        }
    }
}

// ---------------- launch ----------------
extern "C" void kernel_launch(void* const* d_in, const int* in_sizes, int n_in,
                              void* d_out, int out_size)
{
    const float* x  = (const float*)d_in[0];
    const int*   ei = (const int*)d_in[1];
    const float* wq = (const float*)d_in[2];
    const float* bq = (const float*)d_in[3];
    const float* wk = (const float*)d_in[4];
    const float* bk = (const float*)d_in[5];
    const float* wv = (const float*)d_in[6];
    const float* bv = (const float*)d_in[7];
    const float* wo = (const float*)d_in[8];
    const float* bo = (const float*)d_in[9];
    float* out = (float*)d_out;

    cudaFuncSetAttribute(proj_mma_kernel,
                         cudaFuncAttributeMaxDynamicSharedMemorySize, PROJ_SMEM);
    cudaFuncSetAttribute(out_mma_kernel,
                         cudaFuncAttributeMaxDynamicSharedMemorySize, OUT_SMEM);

    prep_kernel<<<6250, 256>>>(wq, bq, wk, bk, wv, bv);
    proj_mma_kernel<<<(N_NODES + 127) / 128, 256, PROJ_SMEM>>>(x);
    edge_kernel<<<(N_EDGES / 4) / 8, 256>>>(ei);
    out_mma_kernel<<<(N_NODES + 127) / 128, 256, OUT_SMEM>>>(wo, bo, out);
}

// round 17
// speedup vs baseline: 1.0107x; 1.0107x over previous
#include <cuda_runtime.h>
#include <cuda_fp16.h>
#include <cstdint>

#define N_NODES 50000
#define N_EDGES 800000
#define IN_F 128
#define OUT_F 128
#define HEADS 4
#define HEAD_DIM 32

// ---------------- scratch (device globals; no allocation allowed) ----------------
__device__ __half g_wb[3 * 128 * 128];      // packed qkv weights: [qkv][outcol][f]
__device__ float  g_bb[384];                // packed qkv biases
__device__ __half g_q[N_NODES * IN_F];      // fp16 q/k/v
__device__ __half g_k[N_NODES * IN_F];
__device__ __half g_v[N_NODES * IN_F];
__device__ float  g_den[N_NODES * HEADS];   // segment sum of exp(score)
__device__ float  g_agg[N_NODES * OUT_F];   // UNNORMALIZED sum of exp(s)*v

__device__ __forceinline__ void mma16816(float* c, const uint32_t* a,
                                         uint32_t b0, uint32_t b1) {
    asm volatile(
        "mma.sync.aligned.m16n8k16.row.col.f32.f16.f16.f32 "
        "{%0,%1,%2,%3}, {%4,%5,%6,%7}, {%8,%9}, {%0,%1,%2,%3};"
        : "+f"(c[0]), "+f"(c[1]), "+f"(c[2]), "+f"(c[3])
        : "r"(a[0]), "r"(a[1]), "r"(a[2]), "r"(a[3]), "r"(b0), "r"(b1));
}

// ---------------- prep: zero agg/den + pack qkv weights/biases ---------------
__global__ void prep_kernel(const float* __restrict__ wq, const float* __restrict__ bq,
                            const float* __restrict__ wk, const float* __restrict__ bk,
                            const float* __restrict__ wv, const float* __restrict__ bv) {
    int idx = blockIdx.x * blockDim.x + threadIdx.x;       // 1.6M threads
    if (idx < N_NODES * OUT_F / 4)
        ((float4*)g_agg)[idx] = make_float4(0.f, 0.f, 0.f, 0.f);
    if (idx < N_NODES * HEADS)
        g_den[idx] = 0.f;
    if (idx < 3 * 128 * 128) {
        int arr = idx >> 14;                 // 0=q,1=k,2=v
        int rem = idx & 16383;
        int j = rem >> 7, f = rem & 127;     // out col j = h*32+d
        int h = j >> 5, d = j & 31;
        const float* w = arr == 0 ? wq : arr == 1 ? wk : wv;
        g_wb[idx] = __float2half_rn(w[h * IN_F * HEAD_DIM + f * HEAD_DIM + d]);
    }
    if (idx < 384) {
        int arr = idx >> 7, j = idx & 127;
        const float* b = arr == 0 ? bq : arr == 1 ? bk : bv;
        g_bb[idx] = b[j];
    }
}

// ---------------- tensor-core QKV projection (A staged ONCE from fp32 x) ----
#define LDA 136
#define PROJ_SMEM (2 * 128 * 136 * 2)
__global__ void __launch_bounds__(256) proj_mma_kernel(const float* __restrict__ x) {
    extern __shared__ __half sm[];
    __half* As = sm;                  // [128][LDA]
    __half* Bs = sm + 128 * LDA;      // [128][LDA]
    const int tid = threadIdx.x;
    const int mbase = blockIdx.x * 128;

    {   // load A tile once, fp32 -> fp16 convert in-flight (clamped rows)
        int r = tid >> 1, hoff = (tid & 1) * 64;
        int node = mbase + r; if (node >= N_NODES) node = N_NODES - 1;
        const float4* src = (const float4*)(x + (size_t)node * IN_F + hoff);
        __half2 tmp[32];
#pragma unroll
        for (int i = 0; i < 16; i++) {
            float4 v = src[i];
            tmp[2 * i + 0] = __floats2half2_rn(v.x, v.y);
            tmp[2 * i + 1] = __floats2half2_rn(v.z, v.w);
        }
        uint4* dst = (uint4*)(As + r * LDA + hoff);
#pragma unroll
        for (int i = 0; i < 8; i++) dst[i] = ((const uint4*)tmp)[i];
    }

    const int warp = tid >> 5, lane = tid & 31;
    const int wm = (warp & 3) * 32;
    const int wn = (warp >> 2) * 64;
    const int g = lane >> 2, tg = lane & 3;

    for (int y = 0; y < 3; y++) {
        if (y > 0) __syncthreads();          // all warps done reading prev Bs
        {   // load B tile for this y
            int n = tid >> 1, hoff = (tid & 1) * 64;
            const uint4* src = (const uint4*)(g_wb + y * 16384 + n * 128 + hoff);
            uint4* dst = (uint4*)(Bs + n * LDA + hoff);
#pragma unroll
            for (int i = 0; i < 8; i++) dst[i] = src[i];
        }
        __syncthreads();

        float c[2][8][4];
#pragma unroll
        for (int tm = 0; tm < 2; tm++)
#pragma unroll
            for (int tn = 0; tn < 8; tn++)
#pragma unroll
                for (int i = 0; i < 4; i++) c[tm][tn][i] = 0.f;

#pragma unroll
        for (int ks = 0; ks < 8; ks++) {
            const int k0 = ks * 16 + tg * 2;
            uint32_t a[2][4];
#pragma unroll
            for (int tm = 0; tm < 2; tm++) {
                const __half* ap = As + (wm + tm * 16 + g) * LDA;
                a[tm][0] = *(const uint32_t*)(ap + k0);
                a[tm][1] = *(const uint32_t*)(ap + 8 * LDA + k0);
                a[tm][2] = *(const uint32_t*)(ap + k0 + 8);
                a[tm][3] = *(const uint32_t*)(ap + 8 * LDA + k0 + 8);
            }
#pragma unroll
            for (int tn = 0; tn < 8; tn++) {
                const __half* bp = Bs + (wn + tn * 8 + g) * LDA + k0;
                uint32_t b0 = *(const uint32_t*)(bp);
                uint32_t b1 = *(const uint32_t*)(bp + 8);
#pragma unroll
                for (int tm = 0; tm < 2; tm++)
                    mma16816(c[tm][tn], a[tm], b0, b1);
            }
        }

        __half* outp = (y == 0) ? g_q : (y == 1) ? g_k : g_v;
        const float* bb = g_bb + y * 128;
#pragma unroll
        for (int tn = 0; tn < 8; tn++) {
            const int col = wn + tn * 8 + tg * 2;
            const float2 bias = *(const float2*)(bb + col);
#pragma unroll
            for (int tm = 0; tm < 2; tm++) {
                int row0 = mbase + wm + tm * 16 + g;
                if (row0 < N_NODES)
                    *(__half2*)(outp + (size_t)row0 * IN_F + col) =
                        __floats2half2_rn(c[tm][tn][0] + bias.x, c[tm][tn][1] + bias.y);
                int row1 = row0 + 8;
                if (row1 < N_NODES)
                    *(__half2*)(outp + (size_t)row1 * IN_F + col) =
                        __floats2half2_rn(c[tm][tn][2] + bias.x, c[tm][tn][3] + bias.y);
            }
        }
    }
}

// ---------------- FUSED edge pass, 4 edges per warp -------------------------
__global__ void __launch_bounds__(256) edge_kernel(const int* __restrict__ ei) {
    const int w = (blockIdx.x * blockDim.x + threadIdx.x) >> 5;
    const int lane = threadIdx.x & 31;
    const int e0 = w * 4;
    if (e0 >= N_EDGES) return;

    int se[4], te[4];
#pragma unroll
    for (int i = 0; i < 4; i++) {
        se[i] = __ldg(&ei[e0 + i]);
        te[i] = __ldg(&ei[N_EDGES + e0 + i]);
    }

    float p[4];
#pragma unroll
    for (int i = 0; i < 4; i++) {
        const uint2 qa = ((const uint2*)(g_q + (size_t)te[i] * IN_F))[lane];
        const uint2 ka = ((const uint2*)(g_k + (size_t)se[i] * IN_F))[lane];
        float2 q0 = __half22float2(*(const __half2*)&qa.x);
        float2 q1 = __half22float2(*(const __half2*)&qa.y);
        float2 k0 = __half22float2(*(const __half2*)&ka.x);
        float2 k1 = __half22float2(*(const __half2*)&ka.y);
        p[i] = q0.x * k0.x + q0.y * k0.y + q1.x * k1.x + q1.y * k1.y;
    }

#pragma unroll
    for (int off = 4; off > 0; off >>= 1)
#pragma unroll
        for (int i = 0; i < 4; i++)
            p[i] += __shfl_xor_sync(0xffffffffu, p[i], off);

    float ex[4];
#pragma unroll
    for (int i = 0; i < 4; i++) ex[i] = __expf(p[i]);

#pragma unroll
    for (int i = 0; i < 4; i++) {
        const uint2 va = ((const uint2*)(g_v + (size_t)se[i] * IN_F))[lane];
        float2 v0 = __half22float2(*(const __half2*)&va.x);
        float2 v1 = __half22float2(*(const __half2*)&va.y);
        float* dst = g_agg + (size_t)te[i] * OUT_F + lane * 4;
        asm volatile("red.global.add.v4.f32 [%0], {%1, %2, %3, %4};"
                     :: "l"(dst), "f"(ex[i] * v0.x), "f"(ex[i] * v0.y),
                        "f"(ex[i] * v1.x), "f"(ex[i] * v1.y) : "memory");
    }

    const int i = lane & 7;
    if (i < 4)
        atomicAdd(&g_den[te[i] * HEADS + (lane >> 3)], ex[i]);
}

// ---------------- output GEMM: A-hi x split-B HMMA --------------------------
// out = fp16(agg/den) @ (wo_hi + wo_lo)^T + bo   (A residual dropped:
// adds ~2.4e-4 RMS rel error; smem 139->104KB => 2 CTAs/SM, mma work -33%).
#define OUT_SMEM (3 * 128 * 136 * 2)
__global__ void __launch_bounds__(256) out_mma_kernel(const float* __restrict__ wo,
                                                      const float* __restrict__ bo,
                                                      float* __restrict__ out) {
    extern __shared__ __half sm[];
    __half* Ah = sm;                       // [128][LDA]
    __half* Bh = sm + 128 * LDA;
    __half* Bl = sm + 2 * 128 * LDA;
    const int tid = threadIdx.x;
    const int mbase = blockIdx.x * 128;

    {   // stage B tiles: read wo fp32 row n (= [outcol][f], fragment-ready), split
        int n = tid >> 1, hoff = (tid & 1) * 64;
        const float4* src = (const float4*)(wo + n * 128 + hoff);
        __half* bh = Bh + n * LDA + hoff;
        __half* bl = Bl + n * LDA + hoff;
#pragma unroll
        for (int i = 0; i < 16; i++) {      // 16 float4 = 64 cols
            float4 v = src[i];
            __half h0 = __float2half_rn(v.x), h1 = __float2half_rn(v.y);
            __half h2 = __float2half_rn(v.z), h3 = __float2half_rn(v.w);
            ((__half2*)(bh + i * 4))[0] = __halves2half2(h0, h1);
            ((__half2*)(bh + i * 4))[1] = __halves2half2(h2, h3);
            ((__half2*)(bl + i * 4))[0] = __floats2half2_rn(
                v.x - __half2float(h0), v.y - __half2float(h1));
            ((__half2*)(bl + i * 4))[1] = __floats2half2_rn(
                v.z - __half2float(h2), v.w - __half2float(h3));
        }
    }
    {   // stage A tile: normalize agg, fp16 (hi only)
        int r = tid >> 1, hoff = (tid & 1) * 64;
        int node = mbase + r; if (node >= N_NODES) node = N_NODES - 1;
        const float* dn = g_den + node * HEADS;
        float rc[2];                        // heads hoff/32, hoff/32+1
#pragma unroll
        for (int hh = 0; hh < 2; hh++) {
            float d = dn[(hoff >> 5) + hh];
            rc[hh] = d > 0.f ? __frcp_rn(d) : 0.f;
        }
        const float4* src = (const float4*)(g_agg + (size_t)node * OUT_F + hoff);
        __half* ah = Ah + r * LDA + hoff;
#pragma unroll
        for (int i = 0; i < 16; i++) {      // 16 float4 = 64 cols
            float4 v = src[i];
            float rr = rc[i >> 3];          // head boundary at col 32 (i=8)
            ((__half2*)(ah + i * 4))[0] = __floats2half2_rn(v.x * rr, v.y * rr);
            ((__half2*)(ah + i * 4))[1] = __floats2half2_rn(v.z * rr, v.w * rr);
        }
    }
    __syncthreads();

    const int warp = tid >> 5, lane = tid & 31;
    const int wm = (warp & 3) * 32;
    const int wn = (warp >> 2) * 64;
    const int g = lane >> 2, tg = lane & 3;

    float c[2][8][4];
#pragma unroll
    for (int tm = 0; tm < 2; tm++)
#pragma unroll
        for (int tn = 0; tn < 8; tn++)
#pragma unroll
            for (int i = 0; i < 4; i++) c[tm][tn][i] = 0.f;

#pragma unroll
    for (int ks = 0; ks < 8; ks++) {
        const int k0 = ks * 16 + tg * 2;
        uint32_t a[2][4];
#pragma unroll
        for (int tm = 0; tm < 2; tm++) {
            const __half* ap = Ah + (wm + tm * 16 + g) * LDA;
            a[tm][0] = *(const uint32_t*)(ap + k0);
            a[tm][1] = *(const uint32_t*)(ap + 8 * LDA + k0);
            a[tm][2] = *(const uint32_t*)(ap + k0 + 8);
            a[tm][3] = *(const uint32_t*)(ap + 8 * LDA + k0 + 8);
        }
#pragma unroll
        for (int tn = 0; tn < 8; tn++) {
            const __half* bph = Bh + (wn + tn * 8 + g) * LDA + k0;
            const __half* bpl = Bl + (wn + tn * 8 + g) * LDA + k0;
            uint32_t bh0 = *(const uint32_t*)(bph);
            uint32_t bh1 = *(const uint32_t*)(bph + 8);
            uint32_t bl0 = *(const uint32_t*)(bpl);
            uint32_t bl1 = *(const uint32_t*)(bpl + 8);
#pragma unroll
            for (int tm = 0; tm < 2; tm++) {
                mma16816(c[tm][tn], a[tm], bl0, bl1);    // small term first
                mma16816(c[tm][tn], a[tm], bh0, bh1);
            }
        }
    }

#pragma unroll
    for (int tn = 0; tn < 8; tn++) {
        const int col = wn + tn * 8 + tg * 2;
        const float2 bias = *(const float2*)(bo + col);
#pragma unroll
        for (int tm = 0; tm < 2; tm++) {
            int row0 = mbase + wm + tm * 16 + g;
            if (row0 < N_NODES)
                *(float2*)(out + (size_t)row0 * OUT_F + col) =
                    make_float2(c[tm][tn][0] + bias.x, c[tm][tn][1] + bias.y);
            int row1 = row0 + 8;
            if (row1 < N_NODES)
                *(float2*)(out + (size_t)row1 * OUT_F + col) =
                    make_float2(c[tm][tn][2] + bias.x, c[tm][tn][3] + bias.y);
        }
    }
}

// ---------------- launch ----------------
extern "C" void kernel_launch(void* const* d_in, const int* in_sizes, int n_in,
                              void* d_out, int out_size)
{
    const float* x  = (const float*)d_in[0];
    const int*   ei = (const int*)d_in[1];
    const float* wq = (const float*)d_in[2];
    const float* bq = (const float*)d_in[3];
    const float* wk = (const float*)d_in[4];
    const float* bk = (const float*)d_in[5];
    const float* wv = (const float*)d_in[6];
    const float* bv = (const float*)d_in[7];
    const float* wo = (const float*)d_in[8];
    const float* bo = (const float*)d_in[9];
    float* out = (float*)d_out;

    cudaFuncSetAttribute(proj_mma_kernel,
                         cudaFuncAttributeMaxDynamicSharedMemorySize, PROJ_SMEM);
    cudaFuncSetAttribute(out_mma_kernel,
                         cudaFuncAttributeMaxDynamicSharedMemorySize, OUT_SMEM);

    prep_kernel<<<6250, 256>>>(wq, bq, wk, bk, wv, bv);
    proj_mma_kernel<<<(N_NODES + 127) / 128, 256, PROJ_SMEM>>>(x);
    edge_kernel<<<(N_EDGES / 4) / 8, 256>>>(ei);
    out_mma_kernel<<<(N_NODES + 127) / 128, 256, OUT_SMEM>>>(wo, bo, out);
}